// round 7
// baseline (speedup 1.0000x reference)
#include <cuda_runtime.h>

#define HH 1024
#define WW 1024
#define NIMG 12
#define RAD 40
#define PLANE (HH * WW)
#define NTOT (NIMG * PLANE)
#define EPSV 1e-3f

#define STRIP 256        // scan strip width (== blockDim.x)
#define OUTW  176        // output columns per block (STRIP - 2*RAD)
#define VSEG  64         // output rows per block (even; 2 rows per iteration)
#define NBX   6          // ceil(1024 / 176)

// Scratch: pointwise a, b (only intermediate that touches DRAM).
__device__ float g_ab[2][NTOT];

// ---------------------------------------------------------------------------
// K1: vertical sliding-window sums of {I, P, I*P, I*I} streamed from GMEM,
//     horizontal box sum via ONE block scan per TWO rows, a,b pointwise out.
// ---------------------------------------------------------------------------
__global__ void __launch_bounds__(256) gf_k1(const float* __restrict__ I,
                                             const float* __restrict__ P) {
    const int img = blockIdx.z;
    const int tid = threadIdx.x;
    const int lane = tid & 31, wid = tid >> 5;
    const int c  = blockIdx.x * OUTW - RAD + tid;
    const int r0 = blockIdx.y * VSEG;
    const float cm = (c >= 0 && c < WW) ? 1.0f : 0.0f;
    const int cc = min(max(c, 0), WW - 1);
    const float* Ip = I + (size_t)img * PLANE + cc;
    const float* Pp = P + (size_t)img * PLANE + cc;

    __shared__ float4 psA[STRIP + 1], psB[STRIP + 1];
    __shared__ float4 wsA[8], wsB[8];

    // init vertical window rows [r0-RAD, r0+RAD]
    float4 s = make_float4(0.f, 0.f, 0.f, 0.f);
#pragma unroll 4
    for (int k = 0; k < 2 * RAD + 1; ++k) {
        const int rw = r0 - RAD + k;
        const float rm = (rw >= 0 && rw < HH) ? cm : 0.0f;
        const size_t o = (size_t)min(max(rw, 0), HH - 1) * WW;
        const float iv = rm * __ldg(Ip + o);
        const float pv = rm * __ldg(Pp + o);
        s.x += iv; s.y += pv; s.z += iv * pv; s.w += iv * iv;
    }

    const float cx = (float)(min(c + RAD, WW - 1) - max(c - RAD, 0) + 1);
    const bool is_out = (tid >= RAD) && (tid < RAD + OUTW) && (c < WW);

    for (int rr = r0; rr < r0 + VSEG; rr += 2) {
        // batched streaming updates for rows rr->rr+1 and rr+1->rr+2 (8 LDGs)
        const int ar0 = rr + RAD + 1,     sr0 = rr - RAD;
        const int ar1 = rr + RAD + 2,     sr1 = rr + 1 - RAD;
        const float am0 = (ar0 < HH) ? cm : 0.0f, sm0 = (sr0 >= 0) ? cm : 0.0f;
        const float am1 = (ar1 < HH) ? cm : 0.0f, sm1 = (sr1 >= 0) ? cm : 0.0f;
        const size_t oa0 = (size_t)min(ar0, HH - 1) * WW;
        const size_t os0 = (size_t)max(sr0, 0) * WW;
        const size_t oa1 = (size_t)min(ar1, HH - 1) * WW;
        const size_t os1 = (size_t)max(sr1, 0) * WW;
        const float ai0 = am0 * __ldg(Ip + oa0), ap0 = am0 * __ldg(Pp + oa0);
        const float si0 = sm0 * __ldg(Ip + os0), sp0 = sm0 * __ldg(Pp + os0);
        const float ai1 = am1 * __ldg(Ip + oa1), ap1 = am1 * __ldg(Pp + oa1);
        const float si1 = sm1 * __ldg(Ip + os1), sp1 = sm1 * __ldg(Pp + os1);

        float4 vA = s;                               // window sums @ row rr
        float4 vB;                                   // window sums @ row rr+1
        vB.x = vA.x + ai0 - si0;
        vB.y = vA.y + ap0 - sp0;
        vB.z = vA.z + ai0 * ap0 - si0 * sp0;
        vB.w = vA.w + ai0 * ai0 - si0 * si0;
        // advance window to row rr+2 for next iteration
        s.x = vB.x + ai1 - si1;
        s.y = vB.y + ap1 - sp1;
        s.z = vB.z + ai1 * ap1 - si1 * sp1;
        s.w = vB.w + ai1 * ai1 - si1 * si1;

        // --- combined 8-channel block scan (rows rr, rr+1) ---
#pragma unroll
        for (int o = 1; o < 32; o <<= 1) {
            float ax = __shfl_up_sync(0xFFFFFFFFu, vA.x, o);
            float ay = __shfl_up_sync(0xFFFFFFFFu, vA.y, o);
            float az = __shfl_up_sync(0xFFFFFFFFu, vA.z, o);
            float aw = __shfl_up_sync(0xFFFFFFFFu, vA.w, o);
            float bx = __shfl_up_sync(0xFFFFFFFFu, vB.x, o);
            float by = __shfl_up_sync(0xFFFFFFFFu, vB.y, o);
            float bz = __shfl_up_sync(0xFFFFFFFFu, vB.z, o);
            float bw = __shfl_up_sync(0xFFFFFFFFu, vB.w, o);
            if (lane >= o) {
                vA.x += ax; vA.y += ay; vA.z += az; vA.w += aw;
                vB.x += bx; vB.y += by; vB.z += bz; vB.w += bw;
            }
        }
        if (lane == 31) { wsA[wid] = vA; wsB[wid] = vB; }
        __syncthreads();
        if (tid < 8) {
            float4 wA = wsA[tid], wB = wsB[tid];
#pragma unroll
            for (int o = 1; o < 8; o <<= 1) {
                float ax = __shfl_up_sync(0xFFu, wA.x, o);
                float ay = __shfl_up_sync(0xFFu, wA.y, o);
                float az = __shfl_up_sync(0xFFu, wA.z, o);
                float aw = __shfl_up_sync(0xFFu, wA.w, o);
                float bx = __shfl_up_sync(0xFFu, wB.x, o);
                float by = __shfl_up_sync(0xFFu, wB.y, o);
                float bz = __shfl_up_sync(0xFFu, wB.z, o);
                float bw = __shfl_up_sync(0xFFu, wB.w, o);
                if (tid >= o) {
                    wA.x += ax; wA.y += ay; wA.z += az; wA.w += aw;
                    wB.x += bx; wB.y += by; wB.z += bz; wB.w += bw;
                }
            }
            wsA[tid] = wA; wsB[tid] = wB;
        }
        __syncthreads();
        float4 oA = (wid > 0) ? wsA[wid - 1] : make_float4(0.f, 0.f, 0.f, 0.f);
        float4 oB = (wid > 0) ? wsB[wid - 1] : make_float4(0.f, 0.f, 0.f, 0.f);
        psA[tid + 1] = make_float4(oA.x + vA.x, oA.y + vA.y, oA.z + vA.z, oA.w + vA.w);
        psB[tid + 1] = make_float4(oB.x + vB.x, oB.y + vB.y, oB.z + vB.z, oB.w + vB.w);
        if (tid == 0) {
            psA[0] = make_float4(0.f, 0.f, 0.f, 0.f);
            psB[0] = make_float4(0.f, 0.f, 0.f, 0.f);
        }
        __syncthreads();

        if (is_out) {
            const size_t ob = (size_t)img * PLANE + (size_t)rr * WW + c;
#pragma unroll
            for (int q = 0; q < 2; ++q) {
                const float4 h4 = q ? psB[tid + RAD + 1] : psA[tid + RAD + 1];
                const float4 l4 = q ? psB[tid - RAD]     : psA[tid - RAD];
                const int r = rr + q;
                const float cy  = (float)(min(r + RAD, HH - 1) - max(r - RAD, 0) + 1);
                const float inv = 1.0f / (cx * cy);
                const float mI  = (h4.x - l4.x) * inv;
                const float mP  = (h4.y - l4.y) * inv;
                const float mIP = (h4.z - l4.z) * inv;
                const float mII = (h4.w - l4.w) * inv;
                const float varI = mII - mI * mI;
                const float a = (mIP - mI * mP) / (varI + EPSV);
                const float b = mP - a * mI;
                g_ab[0][ob + (size_t)q * WW] = a;
                g_ab[1][ob + (size_t)q * WW] = b;
            }
        }
    }
}

// ---------------------------------------------------------------------------
// K2: vertical sliding sums of {a, b}, horizontal box via ONE block scan per
//     TWO rows, fused output: out = mean_a * I + mean_b.
// ---------------------------------------------------------------------------
__global__ void __launch_bounds__(256) gf_k2(const float* __restrict__ I,
                                             float* __restrict__ out) {
    const int img = blockIdx.z;
    const int tid = threadIdx.x;
    const int lane = tid & 31, wid = tid >> 5;
    const int c  = blockIdx.x * OUTW - RAD + tid;
    const int r0 = blockIdx.y * VSEG;
    const float cm = (c >= 0 && c < WW) ? 1.0f : 0.0f;
    const int cc = min(max(c, 0), WW - 1);
    const size_t pb = (size_t)img * PLANE + cc;
    const float* pa = g_ab[0] + pb;
    const float* pbv = g_ab[1] + pb;

    __shared__ float4 ps[STRIP + 1];
    __shared__ float4 ws[8];

    float2 s = make_float2(0.f, 0.f);
#pragma unroll 4
    for (int k = 0; k < 2 * RAD + 1; ++k) {
        const int rw = r0 - RAD + k;
        const float rm = (rw >= 0 && rw < HH) ? cm : 0.0f;
        const size_t o = (size_t)min(max(rw, 0), HH - 1) * WW;
        s.x += rm * __ldg(pa + o);
        s.y += rm * __ldg(pbv + o);
    }

    const float cx = (float)(min(c + RAD, WW - 1) - max(c - RAD, 0) + 1);
    const bool is_out = (tid >= RAD) && (tid < RAD + OUTW) && (c < WW);

    for (int rr = r0; rr < r0 + VSEG; rr += 2) {
        const int ar0 = rr + RAD + 1,  sr0 = rr - RAD;
        const int ar1 = rr + RAD + 2,  sr1 = rr + 1 - RAD;
        const float am0 = (ar0 < HH) ? cm : 0.0f, sm0 = (sr0 >= 0) ? cm : 0.0f;
        const float am1 = (ar1 < HH) ? cm : 0.0f, sm1 = (sr1 >= 0) ? cm : 0.0f;
        const size_t oa0 = (size_t)min(ar0, HH - 1) * WW;
        const size_t os0 = (size_t)max(sr0, 0) * WW;
        const size_t oa1 = (size_t)min(ar1, HH - 1) * WW;
        const size_t os1 = (size_t)max(sr1, 0) * WW;
        const float aa0 = am0 * __ldg(pa + oa0), ab0 = am0 * __ldg(pbv + oa0);
        const float sa0 = sm0 * __ldg(pa + os0), sb0 = sm0 * __ldg(pbv + os0);
        const float aa1 = am1 * __ldg(pa + oa1), ab1 = am1 * __ldg(pbv + oa1);
        const float sa1 = sm1 * __ldg(pa + os1), sb1 = sm1 * __ldg(pbv + os1);
        const size_t ib = (size_t)img * PLANE + (size_t)rr * WW + c;
        const float iv0 = is_out ? __ldg(I + ib) : 0.0f;
        const float iv1 = is_out ? __ldg(I + ib + WW) : 0.0f;

        // v = (a@rr, b@rr, a@rr+1, b@rr+1)
        float4 v;
        v.x = s.x;             v.y = s.y;
        v.z = s.x + aa0 - sa0; v.w = s.y + ab0 - sb0;
        s.x = v.z + aa1 - sa1;
        s.y = v.w + ab1 - sb1;

#pragma unroll
        for (int o = 1; o < 32; o <<= 1) {
            float nx = __shfl_up_sync(0xFFFFFFFFu, v.x, o);
            float ny = __shfl_up_sync(0xFFFFFFFFu, v.y, o);
            float nz = __shfl_up_sync(0xFFFFFFFFu, v.z, o);
            float nw = __shfl_up_sync(0xFFFFFFFFu, v.w, o);
            if (lane >= o) { v.x += nx; v.y += ny; v.z += nz; v.w += nw; }
        }
        if (lane == 31) ws[wid] = v;
        __syncthreads();
        if (tid < 8) {
            float4 w = ws[tid];
#pragma unroll
            for (int o = 1; o < 8; o <<= 1) {
                float nx = __shfl_up_sync(0xFFu, w.x, o);
                float ny = __shfl_up_sync(0xFFu, w.y, o);
                float nz = __shfl_up_sync(0xFFu, w.z, o);
                float nw = __shfl_up_sync(0xFFu, w.w, o);
                if (tid >= o) { w.x += nx; w.y += ny; w.z += nz; w.w += nw; }
            }
            ws[tid] = w;
        }
        __syncthreads();
        float4 off = (wid > 0) ? ws[wid - 1] : make_float4(0.f, 0.f, 0.f, 0.f);
        ps[tid + 1] = make_float4(off.x + v.x, off.y + v.y, off.z + v.z, off.w + v.w);
        if (tid == 0) ps[0] = make_float4(0.f, 0.f, 0.f, 0.f);
        __syncthreads();

        if (is_out) {
            const float4 h4 = ps[tid + RAD + 1];
            const float4 l4 = ps[tid - RAD];
            const float cy0 = (float)(min(rr + RAD, HH - 1) - max(rr - RAD, 0) + 1);
            const float cy1 = (float)(min(rr + 1 + RAD, HH - 1) - max(rr + 1 - RAD, 0) + 1);
            const float inv0 = 1.0f / (cx * cy0);
            const float inv1 = 1.0f / (cx * cy1);
            const size_t ob = (size_t)img * PLANE + (size_t)rr * WW + c;
            out[ob]      = ((h4.x - l4.x) * inv0) * iv0 + ((h4.y - l4.y) * inv0);
            out[ob + WW] = ((h4.z - l4.z) * inv1) * iv1 + ((h4.w - l4.w) * inv1);
        }
    }
}

extern "C" void kernel_launch(void* const* d_in, const int* in_sizes, int n_in,
                              void* d_out, int out_size) {
    const float* I = (const float*)d_in[0];
    const float* P = (const float*)d_in[1];
    float* out = (float*)d_out;

    dim3 grid(NBX, HH / VSEG, NIMG);
    gf_k1<<<grid, 256>>>(I, P);
    gf_k2<<<grid, 256>>>(I, out);
}